// round 17
// baseline (speedup 1.0000x reference)
#include <cuda_runtime.h>
#include <cuda_bf16.h>
#include <math.h>
#include <stdint.h>

#define BB 64
#define COMBC 770
#define DMODEL 1282
#define DINNER 2564
#define DSTATE 16
#define MSEQ 16384
#define LDSEQ 1312      // padded d_model (41*32)
#define DBL_LD 116

// ---------------- scratch (device globals; no allocations allowed) ----------------
__device__ __align__(128) float g_seq[(size_t)MSEQ * LDSEQ];     // padded, pad cols zeroed
__device__ __align__(128) float g_tmp0[(size_t)MSEQ * 128];
__device__ __align__(128) float g_y0[BB * 128];
__device__ __align__(128) float g_pooled[(size_t)17600 * COMBC];
__device__ __align__(128) float g_yp[(size_t)17600 * 128];
__device__ __align__(128) float g_xz[(size_t)MSEQ * 2 * DINNER];
__device__ __align__(128) float g_u[(size_t)MSEQ * DINNER];
__device__ __align__(128) float g_dbl[(size_t)MSEQ * DBL_LD];
__device__ __align__(128) float g_dtv[(size_t)MSEQ * DINNER];
__device__ __align__(128) float g_bn[1024];

// hi/lo bf16 chunk-interleaved operands: [(m*nch + c)*64 + j], j<32 hi(k=c*32+j), j>=32 lo
__device__ __align__(128) __nv_bfloat16 g_seqhl [(size_t)MSEQ * 41 * 64];
__device__ __align__(128) __nv_bfloat16 g_winhl [(size_t)5376 * 41 * 64];
__device__ __align__(128) __nv_bfloat16 g_uhl   [(size_t)MSEQ * 81 * 64];
__device__ __align__(128) __nv_bfloat16 g_xwhl  [(size_t)128  * 81 * 64];
__device__ __align__(128) __nv_bfloat16 g_dblhl [(size_t)MSEQ * 3  * 64];
__device__ __align__(128) __nv_bfloat16 g_dtwhl [(size_t)2816 * 3  * 64];
__device__ __align__(128) __nv_bfloat16 g_yshl  [(size_t)MSEQ * 81 * 64];
__device__ __align__(128) __nv_bfloat16 g_wouthl[(size_t)1536 * 81 * 64];
__device__ __align__(128) __nv_bfloat16 g_combhl[(size_t)MSEQ * 25 * 64];
__device__ __align__(128) __nv_bfloat16 g_cw0hl [(size_t)128  * 25 * 64];

// ================= helpers =================
__device__ __forceinline__ uint32_t smem_u32(const void* p) {
    uint32_t a;
    asm("{ .reg .u64 t; cvta.to.shared.u64 t, %1; cvt.u32.u64 %0, t; }" : "=r"(a) : "l"(p));
    return a;
}
__device__ __forceinline__ void ldsm4(uint32_t& r0, uint32_t& r1, uint32_t& r2, uint32_t& r3,
                                      uint32_t addr) {
    asm volatile("ldmatrix.sync.aligned.m8n8.x4.shared.b16 {%0,%1,%2,%3}, [%4];"
                 : "=r"(r0), "=r"(r1), "=r"(r2), "=r"(r3) : "r"(addr));
}
__device__ __forceinline__ void mma_bf16(float* d, const uint32_t* a, const uint32_t* b) {
    asm volatile(
        "mma.sync.aligned.m16n8k16.row.col.f32.bf16.bf16.f32 "
        "{%0,%1,%2,%3}, {%4,%5,%6,%7}, {%8,%9}, {%0,%1,%2,%3};"
        : "+f"(d[0]), "+f"(d[1]), "+f"(d[2]), "+f"(d[3])
        : "r"(a[0]), "r"(a[1]), "r"(a[2]), "r"(a[3]), "r"(b[0]), "r"(b[1]));
}
__device__ __forceinline__ void split2(float x, float y, __nv_bfloat162& hi, __nv_bfloat162& lo) {
    hi.x = __float2bfloat16(x); hi.y = __float2bfloat16(y);
    lo.x = __float2bfloat16(x - __bfloat162float(hi.x));
    lo.y = __float2bfloat16(y - __bfloat162float(hi.y));
}
__device__ __forceinline__ void cpasync16(uint32_t s, const void* g) {
    asm volatile("cp.async.cg.shared.global [%0], [%1], 16;" :: "r"(s), "l"(g));
}
#define CP_COMMIT() asm volatile("cp.async.commit_group;" ::: "memory")
#define CP_WAIT1()  asm volatile("cp.async.wait_group 1;" ::: "memory")

// ---------------- generic fp32 -> hi/lo chunked convert ----------------
__global__ void k_cvt(const float* __restrict__ src, __nv_bfloat16* __restrict__ dst,
                      int Mreal, int Kreal, int lds, int nch, int total) {
    int i = blockIdx.x * 256 + threadIdx.x;
    if (i >= total) return;
    int jp = i & 15;
    int t = i >> 4;
    int c = t % nch;
    int m = t / nch;
    int k = c * 32 + jp * 2;
    float f0 = 0.f, f1 = 0.f;
    if (m < Mreal) {
        if (k < Kreal)     f0 = src[(size_t)m * lds + k];
        if (k + 1 < Kreal) f1 = src[(size_t)m * lds + k + 1];
    }
    __nv_bfloat162 hi, lo;
    split2(f0, f1, hi, lo);
    size_t base = ((size_t)(m * nch + c)) * 64 + jp * 2;
    *(__nv_bfloat162*)&dst[base]      = hi;
    *(__nv_bfloat162*)&dst[base + 32] = lo;
}

// ===== wgemm2: cp.async-pipelined bf16-split GEMM, 128x128 tile, 3 stages x 32KB =====
// EPI: 2 x_proj (remap fp32 + dbl_hl), 4 BN+ReLU6
#define WS2 98304

template<int EPI>
__global__ __launch_bounds__(256, 2) void wgemm2(
    const __nv_bfloat16* __restrict__ Ahl, const __nv_bfloat16* __restrict__ Bhl,
    float* __restrict__ C, int Nreal, int ldc, int nch, const float* __restrict__ aux)
{
    extern __shared__ char smem[];
    const int tid = threadIdx.x;
    const int wid = tid >> 5;
    const int lane = tid & 31;
    const int wm = wid >> 2, wn = wid & 3;
    const int row0 = blockIdx.y * 128;
    const int col0 = blockIdx.x * 128;
    const uint32_t sb = smem_u32(smem);

    const int cp_r0 = tid >> 3, cp_c8 = tid & 7;
    const uint32_t cp_sw = (uint32_t)((cp_c8 ^ (cp_r0 & 7)) << 4);

    auto issue = [&](int c, int s) {
        const uint32_t st = sb + s * 32768;
        const size_t ga = ((size_t)(row0 + cp_r0) * nch + c) * 64 + cp_c8 * 8;
        const size_t gb = ((size_t)(col0 + cp_r0) * nch + c) * 64 + cp_c8 * 8;
#pragma unroll
        for (int q = 0; q < 4; q++) {
            uint32_t so = (uint32_t)((cp_r0 + q * 32) * 128) + cp_sw;
            cpasync16(st + so,         Ahl + ga + (size_t)q * 32 * nch * 64);
            cpasync16(st + 16384 + so, Bhl + gb + (size_t)q * 32 * nch * 64);
        }
    };

    const int r3 = lane & 7;
    const uint32_t aRowB = (uint32_t)((wm * 64 + r3 + ((lane >> 3) & 1) * 8) * 128);
    const int aSel = (lane >> 4) & 1;
    const uint32_t bRowB = (uint32_t)(16384 + (wn * 32 + r3 + ((lane >> 4) & 1) * 8) * 128);
    const int bSel = (lane >> 3) & 1;

    float acc[4][4][4];
#pragma unroll
    for (int i = 0; i < 4; i++)
#pragma unroll
        for (int j = 0; j < 4; j++)
#pragma unroll
            for (int q = 0; q < 4; q++) acc[i][j][q] = 0.f;

    issue(0, 0); CP_COMMIT();
    if (nch > 1) issue(1, 1);
    CP_COMMIT();

    for (int c = 0; c < nch; c++) {
        const int s = c % 3;
        CP_WAIT1();
        __syncthreads();
        if (c + 2 < nch) issue(c + 2, (c + 2) % 3);
        CP_COMMIT();
        const uint32_t st = sb + s * 32768;
#pragma unroll
        for (int kk2 = 0; kk2 < 2; kk2++) {
            const int aCh = aSel + kk2 * 2;
            const uint32_t aHi = (uint32_t)((aCh ^ r3) << 4);
            const uint32_t aLo = (uint32_t)(((aCh + 4) ^ r3) << 4);
            const int bCh = bSel + kk2 * 2;
            const uint32_t bHi = (uint32_t)((bCh ^ r3) << 4);
            const uint32_t bLo = (uint32_t)(((bCh + 4) ^ r3) << 4);
            uint32_t bfh[4][2], bfl[4][2];
#pragma unroll
            for (int ntp = 0; ntp < 2; ntp++) {
                uint32_t ba = st + bRowB + ntp * 2048;
                ldsm4(bfh[ntp*2][0], bfh[ntp*2][1], bfh[ntp*2+1][0], bfh[ntp*2+1][1], ba + bHi);
                ldsm4(bfl[ntp*2][0], bfl[ntp*2][1], bfl[ntp*2+1][0], bfl[ntp*2+1][1], ba + bLo);
            }
#pragma unroll
            for (int mp = 0; mp < 2; mp++) {
                uint32_t afh[2][4], afl[2][4];
#pragma unroll
                for (int m2 = 0; m2 < 2; m2++) {
                    uint32_t aa = st + aRowB + (mp * 2 + m2) * 2048;
                    ldsm4(afh[m2][0], afh[m2][1], afh[m2][2], afh[m2][3], aa + aHi);
                    ldsm4(afl[m2][0], afl[m2][1], afl[m2][2], afl[m2][3], aa + aLo);
                }
#pragma unroll
                for (int m2 = 0; m2 < 2; m2++)
#pragma unroll
                    for (int nt = 0; nt < 4; nt++)
                        mma_bf16(acc[mp*2+m2][nt], afh[m2], bfh[nt]);
#pragma unroll
                for (int m2 = 0; m2 < 2; m2++)
#pragma unroll
                    for (int nt = 0; nt < 4; nt++)
                        mma_bf16(acc[mp*2+m2][nt], afl[m2], bfh[nt]);
#pragma unroll
                for (int m2 = 0; m2 < 2; m2++)
#pragma unroll
                    for (int nt = 0; nt < 4; nt++)
                        mma_bf16(acc[mp*2+m2][nt], afh[m2], bfl[nt]);
            }
        }
    }

    const int g = lane >> 2, tq = lane & 3;
#pragma unroll
    for (int mt = 0; mt < 4; mt++) {
        const int m = row0 + wm * 64 + mt * 16 + g;
#pragma unroll
        for (int nt = 0; nt < 4; nt++) {
            const int n = col0 + wn * 32 + nt * 8 + tq * 2;
            float* a4 = acc[mt][nt];
            if (EPI == 2) {
#pragma unroll
                for (int e = 0; e < 4; e++) {
                    int nn = n + (e & 1), mm = m + (e >> 1) * 8;
                    float v = a4[e];
                    if (nn < 81)       C[(size_t)mm * DBL_LD + nn] = v;
                    else if (nn < 113) C[(size_t)mm * DBL_LD + nn + 3] = v;
                    if (nn < 96) {
                        float vv = (nn < 81) ? v : 0.f;
                        __nv_bfloat16 hi = __float2bfloat16(vv);
                        __nv_bfloat16 lo = __float2bfloat16(vv - __bfloat162float(hi));
                        size_t hb = ((size_t)mm * 3 + (nn >> 5)) * 64 + (nn & 31);
                        g_dblhl[hb] = hi; g_dblhl[hb + 32] = lo;
                    }
                }
            } else {
#pragma unroll
                for (int e = 0; e < 4; e++) {
                    int nn = n + (e & 1), mm = m + (e >> 1) * 8;
                    if (nn < Nreal) {
                        float v = a4[e] * aux[nn] + aux[512 + nn];
                        v = fminf(fmaxf(v, 0.f), 6.f);
                        C[(size_t)mm * ldc + nn] = v;
                    }
                }
            }
        }
    }
}

// ===== wgemm3: 128x256 tile, warp tile 64x64, 3 stages x 48KB, 1 CTA/SM =====
// EPI: 0 plain(ldc), 1 (b,n,l) store, 3 bias+softplus
#define WS3 147456

template<int EPI>
__global__ __launch_bounds__(256, 1) void wgemm3(
    const __nv_bfloat16* __restrict__ Ahl, const __nv_bfloat16* __restrict__ Bhl,
    float* __restrict__ C, int Nreal, int ldc, int nch, const float* __restrict__ aux)
{
    extern __shared__ char smem[];
    const int tid = threadIdx.x;
    const int wid = tid >> 5;
    const int lane = tid & 31;
    const int wm = wid >> 2, wn = wid & 3;
    const int row0 = blockIdx.y * 128;
    const int col0 = blockIdx.x * 256;
    const uint32_t sb = smem_u32(smem);

    const int cp_r0 = tid >> 3, cp_c8 = tid & 7;
    const uint32_t cp_sw = (uint32_t)((cp_c8 ^ (cp_r0 & 7)) << 4);

    auto issue = [&](int c, int s) {
        const uint32_t st = sb + s * 49152;
        const size_t ga = ((size_t)(row0 + cp_r0) * nch + c) * 64 + cp_c8 * 8;
        const size_t gb = ((size_t)(col0 + cp_r0) * nch + c) * 64 + cp_c8 * 8;
#pragma unroll
        for (int q = 0; q < 4; q++) {
            uint32_t so = (uint32_t)((cp_r0 + q * 32) * 128) + cp_sw;
            cpasync16(st + so, Ahl + ga + (size_t)q * 32 * nch * 64);
        }
#pragma unroll
        for (int q = 0; q < 8; q++) {
            uint32_t so = (uint32_t)((cp_r0 + q * 32) * 128) + cp_sw;
            cpasync16(st + 16384 + so, Bhl + gb + (size_t)q * 32 * nch * 64);
        }
    };

    const int r3 = lane & 7;
    const uint32_t aRowB = (uint32_t)((wm * 64 + r3 + ((lane >> 3) & 1) * 8) * 128);
    const int aSel = (lane >> 4) & 1;
    const uint32_t bRowB = (uint32_t)(16384 + (wn * 64 + r3 + ((lane >> 4) & 1) * 8) * 128);
    const int bSel = (lane >> 3) & 1;

    float acc[4][8][4];
#pragma unroll
    for (int i = 0; i < 4; i++)
#pragma unroll
        for (int j = 0; j < 8; j++)
#pragma unroll
            for (int q = 0; q < 4; q++) acc[i][j][q] = 0.f;

    issue(0, 0); CP_COMMIT();
    if (nch > 1) issue(1, 1);
    CP_COMMIT();

    for (int c = 0; c < nch; c++) {
        const int s = c % 3;
        CP_WAIT1();
        __syncthreads();
        if (c + 2 < nch) issue(c + 2, (c + 2) % 3);
        CP_COMMIT();
        const uint32_t st = sb + s * 49152;
#pragma unroll
        for (int kk2 = 0; kk2 < 2; kk2++) {
            const int aCh = aSel + kk2 * 2;
            const uint32_t aHi = (uint32_t)((aCh ^ r3) << 4);
            const uint32_t aLo = (uint32_t)(((aCh + 4) ^ r3) << 4);
            const int bCh = bSel + kk2 * 2;
            const uint32_t bHi = (uint32_t)((bCh ^ r3) << 4);
            const uint32_t bLo = (uint32_t)(((bCh + 4) ^ r3) << 4);
            uint32_t bfh[8][2], bfl[8][2];
#pragma unroll
            for (int ntp = 0; ntp < 4; ntp++) {
                uint32_t ba = st + bRowB + ntp * 2048;
                ldsm4(bfh[ntp*2][0], bfh[ntp*2][1], bfh[ntp*2+1][0], bfh[ntp*2+1][1], ba + bHi);
                ldsm4(bfl[ntp*2][0], bfl[ntp*2][1], bfl[ntp*2+1][0], bfl[ntp*2+1][1], ba + bLo);
            }
#pragma unroll
            for (int mp = 0; mp < 2; mp++) {
                uint32_t afh[2][4], afl[2][4];
#pragma unroll
                for (int m2 = 0; m2 < 2; m2++) {
                    uint32_t aa = st + aRowB + (mp * 2 + m2) * 2048;
                    ldsm4(afh[m2][0], afh[m2][1], afh[m2][2], afh[m2][3], aa + aHi);
                    ldsm4(afl[m2][0], afl[m2][1], afl[m2][2], afl[m2][3], aa + aLo);
                }
#pragma unroll
                for (int m2 = 0; m2 < 2; m2++)
#pragma unroll
                    for (int nt = 0; nt < 8; nt++)
                        mma_bf16(acc[mp*2+m2][nt], afh[m2], bfh[nt]);
#pragma unroll
                for (int m2 = 0; m2 < 2; m2++)
#pragma unroll
                    for (int nt = 0; nt < 8; nt++)
                        mma_bf16(acc[mp*2+m2][nt], afl[m2], bfh[nt]);
#pragma unroll
                for (int m2 = 0; m2 < 2; m2++)
#pragma unroll
                    for (int nt = 0; nt < 8; nt++)
                        mma_bf16(acc[mp*2+m2][nt], afh[m2], bfl[nt]);
            }
        }
    }

    const int g = lane >> 2, tq = lane & 3;
#pragma unroll
    for (int mt = 0; mt < 4; mt++) {
        const int m = row0 + wm * 64 + mt * 16 + g;
#pragma unroll
        for (int nt = 0; nt < 8; nt++) {
            const int n = col0 + wn * 64 + nt * 8 + tq * 2;
            float* a4 = acc[mt][nt];
            if (EPI == 0) {
                if (n < Nreal) {
                    *(float2*)&C[(size_t)m * ldc + n] = make_float2(a4[0], a4[1]);
                    *(float2*)&C[(size_t)(m + 8) * ldc + n] = make_float2(a4[2], a4[3]);
                }
            } else if (EPI == 1) {
                if (n < Nreal) {
                    size_t ob = ((size_t)(m >> 8) * DMODEL + n) * 256 + (m & 255);
                    C[ob] = a4[0]; C[ob + 256] = a4[1];
                    C[ob + 8] = a4[2]; C[ob + 256 + 8] = a4[3];
                }
            } else {
#pragma unroll
                for (int e = 0; e < 4; e++) {
                    int nn = n + (e & 1), mm = m + (e >> 1) * 8;
                    if (nn < Nreal) {
                        float v = a4[e] + aux[nn];
                        v = (v > 20.f) ? v : log1pf(__expf(v));
                        C[(size_t)mm * DINNER + nn] = v;
                    }
                }
            }
        }
    }
}

// ================= SIMT pieces =================
__global__ void k_bnprep(const float* __restrict__ gamma, const float* __restrict__ beta,
                         const float* __restrict__ mean, const float* __restrict__ var) {
    int i = threadIdx.x;
    if (i < 512) {
        float inv = rsqrtf(var[i] + 1e-5f) * gamma[i];
        g_bn[i] = inv;
        g_bn[512 + i] = beta[i] - mean[i] * inv;
    }
}

__device__ __forceinline__ float xx_val(int i) { return -0.3f + (0.6f / 15.0f) * (float)i; }

__global__ void k_build(const float* __restrict__ x, const float* __restrict__ pc) {
    __shared__ float tile[32][33];
    int b = blockIdx.x;
    int c0 = blockIdx.y * 32;
    int l0 = blockIdx.z * 32;
    int tx = threadIdx.x, ty = threadIdx.y;
    int c = c0 + ty, l = l0 + tx;
    if (c < COMBC) {
        float v;
        if (c < 512)       v = x[((size_t)(b * 512 + c)) * 256 + l];
        else if (c == 512) v = xx_val(l & 15);
        else if (c == 513) v = xx_val(l >> 4);
        else               v = pc[b * 256 + (c - 514)];
        tile[ty][tx] = v;
    }
    __syncthreads();
    c = c0 + tx; l = l0 + ty;
    if (c < COMBC)
        g_seq[((size_t)(b * 256 + l)) * LDSEQ + c] = tile[tx][ty];
}

// SIMT SGEMM (small pooled PPM convs only). EP=1: BN+ReLU6
template<int EP>
__global__ __launch_bounds__(256, 2) void sgemm(
    const float* __restrict__ A, const float* __restrict__ B, float* __restrict__ C,
    int M, int N, int K, int lda, int ldb, int ldc,
    const float* __restrict__ aux1, const float* __restrict__ aux2)
{
    __shared__ float As[8][128];
    __shared__ float Bs[8][128];
    const int tid = threadIdx.x;
    const int tx = tid & 15, ty = tid >> 4;
    const int row0 = blockIdx.y * 128, col0 = blockIdx.x * 128;
    const int lm = tid >> 1;
    const int lk = (tid & 1) * 4;
    float acc[8][8];
#pragma unroll
    for (int i = 0; i < 8; i++)
#pragma unroll
        for (int j = 0; j < 8; j++) acc[i][j] = 0.f;

    const int gmA = row0 + lm;
    const int gnB = col0 + lm;
    for (int k0 = 0; k0 < K; k0 += 8) {
#pragma unroll
        for (int j = 0; j < 4; j++) {
            int gk = k0 + lk + j;
            As[lk + j][lm] = (gmA < M && gk < K) ? A[(size_t)gmA * lda + gk] : 0.f;
            Bs[lk + j][lm] = (gnB < N && gk < K) ? B[(size_t)gnB * ldb + gk] : 0.f;
        }
        __syncthreads();
#pragma unroll
        for (int kk = 0; kk < 8; kk++) {
            float a[8], bb[8];
#pragma unroll
            for (int i = 0; i < 8; i++) a[i] = As[kk][ty * 8 + i];
#pragma unroll
            for (int j = 0; j < 8; j++) bb[j] = Bs[kk][tx * 8 + j];
#pragma unroll
            for (int i = 0; i < 8; i++)
#pragma unroll
                for (int j = 0; j < 8; j++) acc[i][j] = fmaf(a[i], bb[j], acc[i][j]);
        }
        __syncthreads();
    }
#pragma unroll
    for (int i = 0; i < 8; i++) {
        int gm = row0 + ty * 8 + i;
        if (gm >= M) continue;
#pragma unroll
        for (int j = 0; j < 8; j++) {
            int gn = col0 + tx * 8 + j;
            if (gn >= N) continue;
            float v = acc[i][j];
            v = v * aux1[gn] + aux2[gn];
            v = fminf(fmaxf(v, 0.f), 6.f);
            C[(size_t)gm * ldc + gn] = v;
        }
    }
}

__global__ void k_reduce0() {
    int b = blockIdx.x, d = threadIdx.x;
    float acc = 0.f;
    for (int l = 0; l < 256; l++)
        acc += g_tmp0[((size_t)(b * 256 + l)) * 128 + d];
    g_y0[b * 128 + d] = acc * (1.f / 256.f);
}

__global__ void k_pool() {
    int b = blockIdx.x;
    int spg = blockIdx.y;
    int s, row_base, local;
    if (spg < 25)       { s = 5;  row_base = 0;    local = spg; }
    else if (spg < 106) { s = 9;  row_base = 1600; local = spg - 25; }
    else                { s = 13; row_base = 6784; local = spg - 106; }
    int o = local / s, p = local % s;
    int h0 = (o * 16) / s, h1 = ((o + 1) * 16 + s - 1) / s;
    int w0 = (p * 16) / s, w1 = ((p + 1) * 16 + s - 1) / s;
    float wgt = 1.f / (float)((h1 - h0) * (w1 - w0));
    size_t orow = (size_t)(row_base + b * s * s + local) * COMBC;
    for (int c = threadIdx.x; c < COMBC; c += 256) {
        float acc = 0.f;
        for (int h = h0; h < h1; h++)
            for (int w = w0; w < w1; w++)
                acc += g_seq[((size_t)(b * 256 + h * 16 + w)) * LDSEQ + c];
        g_pooled[orow + c] = acc * wgt;
    }
}

__global__ void k_assemble() {
    int m = blockIdx.x;
    int b = m >> 8, l = m & 255;
    int o = l >> 4, p = l & 15;
    int t = threadIdx.x;
    if (t < 30) g_seq[(size_t)m * LDSEQ + 1282 + t] = 0.f;  // zero K-pad
    if (t < 128) {
        g_seq[(size_t)m * LDSEQ + 770 + t] = g_y0[b * 128 + t];
    } else {
        int i = (t - 128) >> 7;
        int d = (t - 128) & 127;
        int s      = (i == 0) ? 5 : (i == 1) ? 9 : 13;
        int base_r = (i == 0) ? 0 : (i == 1) ? 1600 : 6784;
        float fs = (float)s;
        float so = (o + 0.5f) * fs / 16.0f - 0.5f;
        so = fminf(fmaxf(so, 0.f), fs - 1.0f);
        int h0 = (int)floorf(so); int h1 = min(h0 + 1, s - 1); float fo = so - (float)h0;
        float sp = (p + 0.5f) * fs / 16.0f - 0.5f;
        sp = fminf(fmaxf(sp, 0.f), fs - 1.0f);
        int w0 = (int)floorf(sp); int w1 = min(w0 + 1, s - 1); float fp = sp - (float)w0;
        const float* yb = g_yp + (size_t)(base_r + b * s * s) * 128 + d;
        float v00 = yb[(size_t)(h0 * s + w0) * 128];
        float v01 = yb[(size_t)(h0 * s + w1) * 128];
        float v10 = yb[(size_t)(h1 * s + w0) * 128];
        float v11 = yb[(size_t)(h1 * s + w1) * 128];
        float v = (1.f - fo) * ((1.f - fp) * v00 + fp * v01)
                + fo * ((1.f - fp) * v10 + fp * v11);
        g_seq[(size_t)m * LDSEQ + 898 + i * 128 + d] = v;
    }
}

// depthwise causal conv1d + bias + SiLU; sliding window over l, one thread per (b,d)
__global__ void k_conv1d(const float* __restrict__ w, const float* __restrict__ bias) {
    int b = blockIdx.x;
    int d = blockIdx.y * 256 + threadIdx.x;
    if (d >= 2592) return;
    if (d >= DINNER) {   // zero pads
        __nv_bfloat16 z = __float2bfloat16(0.f);
        for (int l = 0; l < 256; l++) {
            size_t hb = ((size_t)(b * 256 + l) * 81 + (d >> 5)) * 64 + (d & 31);
            g_uhl[hb] = z; g_uhl[hb + 32] = z;
        }
        return;
    }
    float w0 = w[d * 4], w1 = w[d * 4 + 1], w2 = w[d * 4 + 2], w3 = w[d * 4 + 3];
    float bs = bias[d];
    float x0 = 0.f, x1 = 0.f, x2 = 0.f;
    const float* xp = g_xz + (size_t)b * 256 * (2 * DINNER) + d;
    float* up = g_u + (size_t)b * 256 * DINNER + d;
    const int cj = (d >> 5) * 64 + (d & 31);
#pragma unroll 4
    for (int l = 0; l < 256; l++) {
        float x3 = xp[(size_t)l * (2 * DINNER)];
        float acc = bs + w0 * x0 + w1 * x1 + w2 * x2 + w3 * x3;
        x0 = x1; x1 = x2; x2 = x3;
        float v = acc / (1.f + __expf(-acc));
        up[(size_t)l * DINNER] = v;
        size_t hb = ((size_t)(b * 256 + l) * 81) * 64 + cj;
        __nv_bfloat16 hi = __float2bfloat16(v);
        g_uhl[hb] = hi;
        g_uhl[hb + 32] = __float2bfloat16(v - __bfloat162float(hi));
    }
}

// selective scan; writes hi/lo g_yshl directly
__global__ __launch_bounds__(256) void k_scan(const float* __restrict__ A_log,
                                              const float* __restrict__ Dp) {
    int b = blockIdx.y;
    int d = blockIdx.x * 256 + threadIdx.x;
    if (d >= DINNER) {
        if (d < 2592) {
            for (int l = 0; l < 256; l++) {
                size_t hb = ((size_t)(b * 256 + l) * 81 + (d >> 5)) * 64 + (d & 31);
                g_yshl[hb] = __float2bfloat16(0.f);
                g_yshl[hb + 32] = __float2bfloat16(0.f);
            }
        }
        return;
    }
    float A[DSTATE];
#pragma unroll
    for (int n = 0; n < DSTATE; n++) A[n] = -__expf(A_log[d * DSTATE + n]);
    float Dd = Dp[d];
    float h[DSTATE];
#pragma unroll
    for (int n = 0; n < DSTATE; n++) h[n] = 0.f;

    const float* dtp = g_dtv + (size_t)b * 256 * DINNER + d;
    const float* up  = g_u   + (size_t)b * 256 * DINNER + d;
    const float* zp  = g_xz  + (size_t)b * 256 * (2 * DINNER) + DINNER + d;
    const float* bc  = g_dbl + (size_t)b * 256 * DBL_LD;
    const int cj = (d >> 5) * 64 + (d & 31);

    for (int l = 0; l < 256; l++) {
        float dt = dtp[(size_t)l * DINNER];
        float u  = up [(size_t)l * DINNER];
        const float4* bcrow = reinterpret_cast<const float4*>(bc + (size_t)l * DBL_LD + 84);
        float4 Bv0 = bcrow[0], Bv1 = bcrow[1], Bv2 = bcrow[2], Bv3 = bcrow[3];
        float4 Cv0 = bcrow[4], Cv1 = bcrow[5], Cv2 = bcrow[6], Cv3 = bcrow[7];
        float Bm[16] = {Bv0.x,Bv0.y,Bv0.z,Bv0.w, Bv1.x,Bv1.y,Bv1.z,Bv1.w,
                        Bv2.x,Bv2.y,Bv2.z,Bv2.w, Bv3.x,Bv3.y,Bv3.z,Bv3.w};
        float Cm[16] = {Cv0.x,Cv0.y,Cv0.z,Cv0.w, Cv1.x,Cv1.y,Cv1.z,Cv1.w,
                        Cv2.x,Cv2.y,Cv2.z,Cv2.w, Cv3.x,Cv3.y,Cv3.z,Cv3.w};
        float xbu = dt * u;
        float y = 0.f;
#pragma unroll
        for (int n = 0; n < DSTATE; n++) {
            float dA = __expf(dt * A[n]);
            h[n] = dA * h[n] + xbu * Bm[n];
            y += h[n] * Cm[n];
        }
        float z = zp[(size_t)l * (2 * DINNER)];
        float sil = z / (1.f + __expf(-z));
        float v = (y + u * Dd) * sil;
        size_t hb = ((size_t)(b * 256 + l) * 81) * 64 + cj;
        __nv_bfloat16 hi = __float2bfloat16(v);
        g_yshl[hb] = hi;
        g_yshl[hb + 32] = __float2bfloat16(v - __bfloat162float(hi));
    }
}

// ================= launch =================
extern "C" void kernel_launch(void* const* d_in, const int* in_sizes, int n_in,
                              void* d_out, int out_size) {
    (void)in_sizes; (void)n_in; (void)out_size;
    const float* x         = (const float*)d_in[0];
    const float* pc_emb    = (const float*)d_in[1];
    const float* conv_w    = (const float*)d_in[2];
    const float* bn_gamma  = (const float*)d_in[3];
    const float* bn_beta   = (const float*)d_in[4];
    const float* bn_mean   = (const float*)d_in[5];
    const float* bn_var    = (const float*)d_in[6];
    const float* in_proj_w = (const float*)d_in[7];
    const float* conv1d_w  = (const float*)d_in[8];
    const float* conv1d_b  = (const float*)d_in[9];
    const float* x_proj_w  = (const float*)d_in[10];
    const float* dt_proj_w = (const float*)d_in[11];
    const float* dt_proj_b = (const float*)d_in[12];
    const float* A_log     = (const float*)d_in[13];
    const float* Dvec      = (const float*)d_in[14];
    const float* out_proj_w= (const float*)d_in[15];
    float* out = (float*)d_out;

    float *p_seq, *p_tmp0, *p_pooled, *p_yp, *p_xz, *p_dbl, *p_dtv, *p_bn;
    __nv_bfloat16 *p_seqhl, *p_winhl, *p_uhl, *p_xwhl, *p_dblhl, *p_dtwhl, *p_yshl, *p_wouthl;
    __nv_bfloat16 *p_combhl, *p_cw0hl;
    cudaGetSymbolAddress((void**)&p_seq,    g_seq);
    cudaGetSymbolAddress((void**)&p_tmp0,   g_tmp0);
    cudaGetSymbolAddress((void**)&p_pooled, g_pooled);
    cudaGetSymbolAddress((void**)&p_yp,     g_yp);
    cudaGetSymbolAddress((void**)&p_xz,     g_xz);
    cudaGetSymbolAddress((void**)&p_dbl,    g_dbl);
    cudaGetSymbolAddress((void**)&p_dtv,    g_dtv);
    cudaGetSymbolAddress((void**)&p_bn,     g_bn);
    cudaGetSymbolAddress((void**)&p_seqhl,  g_seqhl);
    cudaGetSymbolAddress((void**)&p_winhl,  g_winhl);
    cudaGetSymbolAddress((void**)&p_uhl,    g_uhl);
    cudaGetSymbolAddress((void**)&p_xwhl,   g_xwhl);
    cudaGetSymbolAddress((void**)&p_dblhl,  g_dblhl);
    cudaGetSymbolAddress((void**)&p_dtwhl,  g_dtwhl);
    cudaGetSymbolAddress((void**)&p_yshl,   g_yshl);
    cudaGetSymbolAddress((void**)&p_wouthl, g_wouthl);
    cudaGetSymbolAddress((void**)&p_combhl, g_combhl);
    cudaGetSymbolAddress((void**)&p_cw0hl,  g_cw0hl);

    cudaFuncSetAttribute(wgemm2<2>, cudaFuncAttributeMaxDynamicSharedMemorySize, WS2);
    cudaFuncSetAttribute(wgemm2<4>, cudaFuncAttributeMaxDynamicSharedMemorySize, WS2);
    cudaFuncSetAttribute(wgemm3<0>, cudaFuncAttributeMaxDynamicSharedMemorySize, WS3);
    cudaFuncSetAttribute(wgemm3<1>, cudaFuncAttributeMaxDynamicSharedMemorySize, WS3);
    cudaFuncSetAttribute(wgemm3<3>, cudaFuncAttributeMaxDynamicSharedMemorySize, WS3);

    // weight converts (independent of data path); buffers padded to 256-wide tiles
    k_cvt<<<(5376*41*16 + 255)/256, 256>>>(in_proj_w,  p_winhl,  5128, 1282, 1282, 41, 5376*41*16);
    k_cvt<<<(1536*81*16 + 255)/256, 256>>>(out_proj_w, p_wouthl, 1282, 2564, 2564, 81, 1536*81*16);
    k_cvt<<<(128*81*16  + 255)/256, 256>>>(x_proj_w,   p_xwhl,    113, 2564, 2564, 81, 128*81*16);
    k_cvt<<<(2816*3*16  + 255)/256, 256>>>(dt_proj_w,  p_dtwhl,  2564,   81,   81,  3, 2816*3*16);
    k_cvt<<<(128*25*16  + 255)/256, 256>>>(conv_w,     p_cw0hl,   128,  770,  770, 25, 128*25*16);

    // PPM
    k_bnprep<<<1, 512>>>(bn_gamma, bn_beta, bn_mean, bn_var);
    k_build<<<dim3(64, 25, 8), dim3(32, 32)>>>(x, pc_emb);
    // cbr0 on tensor cores: comb cols 0..770 -> hi/lo (25 chunks), BN+ReLU6 -> g_tmp0
    k_cvt<<<(MSEQ*25*16 + 255)/256, 256>>>(p_seq, p_combhl, MSEQ, 770, LDSEQ, 25, MSEQ*25*16);
    wgemm2<4><<<dim3(1, 128), 256, WS2>>>(p_combhl, p_cw0hl, p_tmp0, 128, 128, 25, p_bn);
    k_reduce0<<<64, 128>>>();
    k_pool<<<dim3(64, 275), 256>>>();
    sgemm<1><<<dim3(1, 13), 256>>>(p_pooled, conv_w + 1 * 128 * COMBC, p_yp,
                                   1600, 128, COMBC, COMBC, COMBC, 128,
                                   p_bn + 128, p_bn + 512 + 128);
    sgemm<1><<<dim3(1, 41), 256>>>(p_pooled + (size_t)1600 * COMBC, conv_w + 2 * 128 * COMBC,
                                   p_yp + (size_t)1600 * 128,
                                   5184, 128, COMBC, COMBC, COMBC, 128,
                                   p_bn + 256, p_bn + 512 + 256);
    sgemm<1><<<dim3(1, 85), 256>>>(p_pooled + (size_t)6784 * COMBC, conv_w + 3 * 128 * COMBC,
                                   p_yp + (size_t)6784 * 128,
                                   10816, 128, COMBC, COMBC, COMBC, 128,
                                   p_bn + 384, p_bn + 512 + 384);
    k_assemble<<<MSEQ, 512>>>();
    k_cvt<<<(MSEQ*41*16 + 255)/256, 256>>>(p_seq, p_seqhl, MSEQ, 1312, LDSEQ, 41, MSEQ*41*16);

    // Mamba
    wgemm3<0><<<dim3(21, 128), 256, WS3>>>(p_seqhl, p_winhl, p_xz, 5128, 5128, 41, nullptr);
    k_conv1d<<<dim3(64, 11), 256>>>(conv1d_w, conv1d_b);
    wgemm2<2><<<dim3(1, 128),  256, WS2>>>(p_uhl, p_xwhl, p_dbl, 113, 0, 81, nullptr);
    wgemm3<3><<<dim3(11, 128), 256, WS3>>>(p_dblhl, p_dtwhl, p_dtv, DINNER, 0, 3, dt_proj_b);
    k_scan<<<dim3(11, 64), 256>>>(A_log, Dvec);
    wgemm3<1><<<dim3(6, 128), 256, WS3>>>(p_yshl, p_wouthl, out, DMODEL, 0, 81, nullptr);
}